// round 9
// baseline (speedup 1.0000x reference)
#include <cuda_runtime.h>
#include <math.h>

// ---------------------------------------------------------------------------
// QECCEqualModel via Givens decomposition (M_k = D1*G*D2):
//   D2 (all bits)  -> per-amp pre-phase at pass1 load (phasor table for r bits)
//   G              -> real Givens rotations
//   D1 bits 0..2   -> per-thread rotation at pass1 store
//   D1 bit 18      -> 8 crots on chunk r3=1 in pass2 dot
//   D1 all other   -> single thread-constant end rotation in pass2
// pass1: G on state bits 0..12, contiguous tiles -> scratch
// pass2: G on states 13..22 (gathered), end-restage to contiguous-per-thread
//        layout, float4 fused dot with code1, last-block reduction -> loss
// ---------------------------------------------------------------------------

#define DIMQ (1u << 23)
typedef unsigned long long u64c;

__device__ u64c     g_scratch[2u * DIMQ];
__device__ float    g_partials[2048 * 4];
__device__ unsigned g_count;               // zero-init; reset by last block

__device__ __forceinline__ u64c pk(float x, float y) {
    u64c r; asm("mov.b64 %0,{%1,%2};" : "=l"(r) : "f"(x), "f"(y)); return r;
}
__device__ __forceinline__ void upk(u64c a, float& x, float& y) {
    asm("mov.b64 {%0,%1},%2;" : "=f"(x), "=f"(y) : "l"(a));
}
__device__ __forceinline__ u64c fma2(u64c a, u64c b, u64c c) {
    u64c r; asm("fma.rn.f32x2 %0,%1,%2,%3;" : "=l"(r) : "l"(a), "l"(b), "l"(c)); return r;
}
__device__ __forceinline__ u64c mul2(u64c a, u64c b) {
    u64c r; asm("mul.rn.f32x2 %0,%1,%2;" : "=l"(r) : "l"(a), "l"(b)); return r;
}
// rotate packed complex a by phasor (cs,sn): (x cs - y sn, y cs + x sn)
__device__ __forceinline__ u64c crot(u64c a, u64c CS, u64c SN) {
    float x, y; upk(a, x, y);
    return fma2(pk(-y, x), SN, mul2(a, CS));
}

// Per-block Givens decomposition of all 23 gates into smem (threads 0..22).
// M = U^T = [[c e^{ia}, -s e^{i(a+d)}],[s e^{ib}, c e^{i(b+d)}]]
__device__ __forceinline__ void decompose(
    int tid, const float* __restrict__ ur, const float* __restrict__ ui,
    float* s_gc, float* s_gs, float* s_pre, float* s_post)
{
    if (tid < 23) {
        int k = tid;
        float m00r = ur[k*4+0], m00i = ui[k*4+0];
        float m01r = ur[k*4+2], m01i = ui[k*4+2];
        float m10r = ur[k*4+1], m10i = ui[k*4+1];
        float m11r = ur[k*4+3], m11i = ui[k*4+3];
        float c = sqrtf(m00r*m00r + m00i*m00i);
        float s = sqrtf(m10r*m10r + m10i*m10i);
        const float eps = 1e-20f;
        float a = (c > eps) ? atan2f(m00i, m00r) : 0.0f;
        float b = (s > eps) ? atan2f(m10i, m10r) : 0.0f;
        float d = (s > eps) ? (atan2f(-m01i, -m01r) - a)
                            : (atan2f(m11i, m11r) - b);
        int j = 22 - k;            // gate k acts on state bit 22-k
        s_gc[j] = c; s_gs[j] = s;
        s_pre[j] = d; s_post[j] = b - a;
    }
}

// Real Givens across a register bit rb: o0 = c*A0 - s*A1 ; o1 = s*A0 + c*A1
__device__ __forceinline__ void reg_gate_r(u64c (&a)[16], int rb, float c, float s)
{
    u64c cc = pk(c, c), ss = pk(s, s), ns = pk(-s, -s);
#pragma unroll
    for (int r0 = 0; r0 < 16; ++r0) {
        if (r0 & (1 << rb)) continue;
        int r1 = r0 | (1 << rb);
        u64c A0 = a[r0], A1 = a[r1];
        a[r0] = fma2(A1, ns, mul2(A0, cc));
        a[r1] = fma2(A1, cc, mul2(A0, ss));
    }
}

// Real Givens across a lane bit: new = c*me + t*other, t = myb ? s : -s
__device__ __forceinline__ void lane_gate_r(u64c (&a)[16], int mask, int myb,
                                            float c, float s)
{
    float t = myb ? s : -s;
    u64c cc = pk(c, c), tt = pk(t, t);
#pragma unroll
    for (int r = 0; r < 16; ++r) {
        float mx, my; upk(a[r], mx, my);
        float ox = __shfl_xor_sync(0xffffffffu, mx, mask);
        float oy = __shfl_xor_sync(0xffffffffu, my, mask);
        a[r] = fma2(pk(ox, oy), tt, mul2(a[r], cc));
    }
}

// ---------------------------------------------------------------------------
// Pass 1: contiguous tiles of 8192 amps. m1 t1=(r<<9)|(w<<5)|lane:
// lane = state 0..4, warp = 5..8, reg = 9..12; restage swaps r<->w.
// Pre-phase: r-bit part (9..12) via 16-entry phasor table, rest one sincos.
// ---------------------------------------------------------------------------
__global__ void __launch_bounds__(512, 2)
pass1_kernel(const float* __restrict__ c0r, const float* __restrict__ c0i,
             const float* __restrict__ ur,  const float* __restrict__ ui)
{
    __shared__ float s_gc[23], s_gs[23], s_pre[23], s_post[23];
    __shared__ float s_pc[16], s_ps[16];
    extern __shared__ u64c sm[];   // 8192 u64 = 64 KB restage buffer

    const int tid  = threadIdx.x;
    decompose(tid, ur, ui, s_gc, s_gs, s_pre, s_post);
    __syncthreads();

    // 16-entry phasor table for pre bits 9..12
    if (tid < 16) {
        float ang = 0.0f;
#pragma unroll
        for (int m = 0; m < 4; ++m)
            ang += (float)((tid >> m) & 1) * s_pre[9 + m];
        float sn, cs; __sincosf(ang, &sn, &cs);
        s_pc[tid] = cs; s_ps[tid] = sn;
    }
    __syncthreads();

    const int lane = tid & 31;
    const int w    = tid >> 5;
    const unsigned bid  = blockIdx.x;
    const unsigned base = bid * 8192u;

    // thread-constant pre-phase (bid bits 0..9 = state bits 13..22)
    float th = 0.0f;
#pragma unroll
    for (int m = 0; m < 10; ++m)
        th += (float)((bid >> m) & 1u) * s_pre[13 + m];
#pragma unroll
    for (int j = 0; j < 5; ++j)
        th += (float)((lane >> j) & 1) * s_pre[j];
#pragma unroll
    for (int m = 0; m < 4; ++m)
        th += (float)((w >> m) & 1) * s_pre[5 + m];
    float snT, csT; __sincosf(th, &snT, &csT);
    const u64c TC = pk(csT, csT), TS = pk(snT, snT);

    u64c a[16];
#pragma unroll
    for (int r = 0; r < 16; ++r) {
        unsigned t1 = (unsigned)(r << 9) | (w << 5) | lane;
        float xr = __ldg(&c0r[base + t1]);
        float xi = __ldg(&c0i[base + t1]);
        u64c x = pk(xr, xi);
        x = crot(x, pk(s_pc[r], s_pc[r]), pk(s_ps[r], s_ps[r]));
        a[r] = crot(x, TC, TS);
    }

#pragma unroll
    for (int j = 0; j < 5; ++j)
        lane_gate_r(a, 1 << j, (lane >> j) & 1, s_gc[j], s_gs[j]);

#pragma unroll
    for (int rb = 0; rb < 4; ++rb)
        reg_gate_r(a, rb, s_gc[9 + rb], s_gs[9 + rb]);

#pragma unroll
    for (int r = 0; r < 16; ++r)
        sm[(unsigned)(r << 9) | (w << 5) | lane] = a[r];
    __syncthreads();
#pragma unroll
    for (int r = 0; r < 16; ++r)
        a[r] = sm[(unsigned)(w << 9) | (r << 5) | lane];

#pragma unroll
    for (int rb = 0; rb < 4; ++rb)
        reg_gate_r(a, rb, s_gc[5 + rb], s_gs[5 + rb]);

    // post-phase for state bits 0..2 (lane bits, thread-constant)
    {
        float th3 = (float)(lane & 1)        * s_post[0]
                  + (float)((lane >> 1) & 1) * s_post[1]
                  + (float)((lane >> 2) & 1) * s_post[2];
        float sn3, cs3; __sincosf(th3, &sn3, &cs3);
        u64c CS = pk(cs3, cs3), SN = pk(sn3, sn3);
#pragma unroll
        for (int r = 0; r < 16; ++r)
            g_scratch[base + ((unsigned)(w << 9) | (r << 5) | lane)]
                = crot(a[r], CS, SN);
    }
}

// ---------------------------------------------------------------------------
// Pass 2: p = b&1 (L2 twin-sharing of c1), l0 = (b>>1)*8.
// m1 t1=(r<<9)|(w<<5)|lane: lane gates states 13,14 (tile3,4);
//   reg gates states 19..22 (tile9..12 = r).
// restage1 (r<->w): m2 t2=(w<<9)|(r<<5)|lane: reg gates states 15..18 (r).
// restage D (swizzled): m3 tile = w<<9 | r3<<8 | lane012<<5 | lane34<<3 | r012
//   -> each thread owns 2 runs of 8 consecutive amps -> float4 dot.
// Post: states 0..2 in pass1; state 18 = r3 -> crot chunk1; rest thread-const.
// Last block: deterministic fixed-order reduction -> out[0].
// ---------------------------------------------------------------------------
__global__ void __launch_bounds__(512, 2)
pass2_kernel(const float* __restrict__ c1r, const float* __restrict__ c1i,
             const float* __restrict__ ur,  const float* __restrict__ ui,
             float* __restrict__ out)
{
    __shared__ float s_gc[23], s_gs[23], s_pre[23], s_post[23];
    __shared__ float red[72];
    __shared__ int   s_isLast;
    extern __shared__ u64c sm[];

    const int tid  = threadIdx.x;
    decompose(tid, ur, ui, s_gc, s_gs, s_pre, s_post);
    __syncthreads();

    const int lane = tid & 31;
    const int w    = tid >> 5;
    const unsigned b  = blockIdx.x;
    const unsigned p  = b & 1u;
    const unsigned l0 = (b >> 1) * 8u;
    const unsigned stateBase = p << 23;

    u64c a[16];
#pragma unroll
    for (int r = 0; r < 16; ++r) {
        unsigned t1 = (unsigned)(r << 9) | (w << 5) | lane;
        unsigned s  = ((t1 >> 3) << 13) + l0 + (t1 & 7u);
        a[r] = g_scratch[stateBase + s];
    }

    // m1: lane gates states 13,14 (tile bits 3,4); reg gates states 19..22
    lane_gate_r(a, 1 << 3, (lane >> 3) & 1, s_gc[13], s_gs[13]);
    lane_gate_r(a, 1 << 4, (lane >> 4) & 1, s_gc[14], s_gs[14]);
#pragma unroll
    for (int rb = 0; rb < 4; ++rb)
        reg_gate_r(a, rb, s_gc[19 + rb], s_gs[19 + rb]);

    // restage1: swap reg bits <-> warp bits
#pragma unroll
    for (int r = 0; r < 16; ++r)
        sm[(unsigned)(r << 9) | (w << 5) | lane] = a[r];
    __syncthreads();
#pragma unroll
    for (int r = 0; r < 16; ++r)
        a[r] = sm[(unsigned)(w << 9) | (r << 5) | lane];

    // m2 reg gates: states 15..18 (tile bits 5..8 = r bits)
#pragma unroll
    for (int rb = 0; rb < 4; ++rb)
        reg_gate_r(a, rb, s_gc[15 + rb], s_gs[15 + rb]);

    // restage D: m2 -> m3 (swizzled: i ^ ((i>>5)&7))
    __syncthreads();   // everyone done reading restage1 data
#pragma unroll
    for (int r = 0; r < 16; ++r) {
        unsigned i = (unsigned)(w << 9) | (r << 5) | lane;
        sm[i ^ ((i >> 5) & 7u)] = a[r];
    }
    __syncthreads();
#pragma unroll
    for (int r = 0; r < 16; ++r) {
        unsigned i = (unsigned)(w << 9) | ((unsigned)(r >> 3) << 8)
                   | (unsigned)(lane & 7) << 5
                   | (unsigned)((lane >> 3) & 3) << 3
                   | (unsigned)(r & 7);
        a[r] = sm[i ^ ((i >> 5) & 7u)];
    }

    // post-phase of state 18 (= r3): rotate chunk r3=1 amps
    {
        float sn18, cs18; __sincosf(s_post[18], &sn18, &cs18);
        u64c CS = pk(cs18, cs18), SN = pk(sn18, sn18);
#pragma unroll
        for (int r = 8; r < 16; ++r)
            a[r] = crot(a[r], CS, SN);
    }

    // vectorized fused dot: 2 chunks of 8 consecutive amps
    float acc0 = 0.f, acc1 = 0.f, acc2 = 0.f, acc3 = 0.f;
#pragma unroll
    for (int c = 0; c < 2; ++c) {
        unsigned hi = (unsigned)(w << 6) | (unsigned)(c << 5)
                    | (unsigned)(lane & 7) << 2 | (unsigned)((lane >> 3) & 3);
        unsigned s0 = (hi << 13) + l0;
#pragma unroll
        for (int h = 0; h < 2; ++h) {
            const float4 X = *(const float4*)(c1r + s0 + h*4);
            const float4 I = *(const float4*)(c1i + s0 + h*4);
            const float4 Y = *(const float4*)(c1r + DIMQ + s0 + h*4);
            const float4 J = *(const float4*)(c1i + DIMQ + s0 + h*4);
            const float* xp = (const float*)&X;
            const float* ip = (const float*)&I;
            const float* yp = (const float*)&Y;
            const float* jp = (const float*)&J;
#pragma unroll
            for (int k = 0; k < 4; ++k) {
                int r = c*8 + h*4 + k;
                float dr, di; upk(a[r], dr, di);
                float xr = xp[k], xi = ip[k];
                acc0 += dr*xr + di*xi;
                acc1 += dr*xi - di*xr;
                float yr = yp[k], yi = jp[k];
                acc2 += dr*yr + di*yi;
                acc3 += dr*yi - di*yr;
            }
        }
    }

    // end rotation: all thread-constant post bits (m3 layout)
    {
        float thc = 0.0f;
#pragma unroll
        for (int m = 0; m < 10; ++m)
            thc += (float)((b >> (1 + m)) & 1u) * s_post[3 + m];
        thc += (float)((lane >> 3) & 1) * s_post[13];   // tile3
        thc += (float)((lane >> 4) & 1) * s_post[14];   // tile4
#pragma unroll
        for (int j = 0; j < 3; ++j)                      // tile5..7
            thc += (float)((lane >> j) & 1) * s_post[15 + j];
#pragma unroll
        for (int m = 0; m < 4; ++m)                      // tile9..12
            thc += (float)((w >> m) & 1) * s_post[19 + m];
        float snc, csc; __sincosf(thc, &snc, &csc);
        float n0 = acc0*csc + acc1*snc, n1 = acc1*csc - acc0*snc;
        float n2 = acc2*csc + acc3*snc, n3 = acc3*csc - acc2*snc;
        acc0 = n0; acc1 = n1; acc2 = n2; acc3 = n3;
    }

#pragma unroll
    for (int o = 16; o > 0; o >>= 1) {
        acc0 += __shfl_xor_sync(0xffffffffu, acc0, o);
        acc1 += __shfl_xor_sync(0xffffffffu, acc1, o);
        acc2 += __shfl_xor_sync(0xffffffffu, acc2, o);
        acc3 += __shfl_xor_sync(0xffffffffu, acc3, o);
    }
    if (lane == 0) {
        red[w*4+0] = acc0; red[w*4+1] = acc1;
        red[w*4+2] = acc2; red[w*4+3] = acc3;
    }
    __syncthreads();
    if (tid < 4) {
        float s = 0.f;
#pragma unroll
        for (int k = 0; k < 16; ++k) s += red[k*4 + tid];
        red[64 + tid] = s;
    }
    __syncthreads();
    if (tid == 0) {
        g_partials[b*4+0] = red[64];
        g_partials[b*4+1] = red[65];
        g_partials[b*4+2] = red[66];
        g_partials[b*4+3] = red[67];
        __threadfence();
        unsigned ticket = atomicAdd(&g_count, 1u);
        s_isLast = (ticket == gridDim.x - 1u) ? 1 : 0;
    }
    __syncthreads();

    if (s_isLast) {
        float acc[8];
#pragma unroll
        for (int j = 0; j < 8; ++j) acc[j] = 0.f;
#pragma unroll
        for (int i = 0; i < 4; ++i) {
            unsigned bb = (unsigned)tid * 4u + i;
            unsigned pq = bb & 1u;
#pragma unroll
            for (int j = 0; j < 4; ++j)
                acc[pq*4 + j] += __ldcg(&g_partials[bb*4 + j]);
        }
#pragma unroll
        for (int o = 16; o > 0; o >>= 1)
#pragma unroll
            for (int j = 0; j < 8; ++j)
                acc[j] += __shfl_xor_sync(0xffffffffu, acc[j], o);
        float* r2 = (float*)sm;
        if (lane == 0)
#pragma unroll
            for (int j = 0; j < 8; ++j) r2[w*8 + j] = acc[j];
        __syncthreads();
        if (tid < 8) {
            float s = 0.f;
#pragma unroll
            for (int k = 0; k < 16; ++k) s += r2[k*8 + tid];
            r2[128 + tid] = s;
        }
        __syncthreads();
        if (tid == 0) {
            float s = 0.f;
#pragma unroll
            for (int j = 0; j < 8; ++j) s += r2[128 + j] * r2[128 + j];
            out[0] = 2.0f - s;
            g_count = 0;               // reset for next graph replay
        }
    }
}

// ---------------------------------------------------------------------------
extern "C" void kernel_launch(void* const* d_in, const int* in_sizes, int n_in,
                              void* d_out, int out_size)
{
    (void)in_sizes; (void)n_in; (void)out_size;
    const float* c0r = (const float*)d_in[0];
    const float* c0i = (const float*)d_in[1];
    const float* c1r = (const float*)d_in[2];
    const float* c1i = (const float*)d_in[3];
    const float* ur  = (const float*)d_in[4];
    const float* ui  = (const float*)d_in[5];

    cudaFuncSetAttribute(pass1_kernel, cudaFuncAttributeMaxDynamicSharedMemorySize, 65536);
    cudaFuncSetAttribute(pass2_kernel, cudaFuncAttributeMaxDynamicSharedMemorySize, 65536);

    pass1_kernel<<<2048, 512, 65536>>>(c0r, c0i, ur, ui);
    pass2_kernel<<<2048, 512, 65536>>>(c1r, c1i, ur, ui, (float*)d_out);
}

// round 10
// speedup vs baseline: 1.1124x; 1.1124x over previous
#include <cuda_runtime.h>
#include <math.h>

// ---------------------------------------------------------------------------
// QECCEqualModel via Givens decomposition (M_k = D1*G*D2):
//   D2 (all bits)       -> per-amp pre-phase at pass1 load
//   G                   -> real Givens rotations
//   D1 bits {0,15,16,17}-> 16-entry phasor table in pass2 dot
//   D1 all other        -> single thread-constant end rotation in pass2
// pass1: G on state bits 0..12, contiguous tiles -> scratch
// pass2: G on states 13..22 (gathered); m2 mapping puts state bit 0 into the
//        register index -> float2-coalesced fused dot with code1;
//        last-block deterministic reduction -> loss  (2 launches total)
// pass2 grid interleaves p in bit0 so p=0/p=1 twins share c1 via L2.
// ---------------------------------------------------------------------------

#define DIMQ (1u << 23)
typedef unsigned long long u64c;

__device__ u64c     g_scratch[2u * DIMQ];
__device__ float    g_partials[2048 * 4];
__device__ unsigned g_count;               // zero-init; reset by last block

__device__ __forceinline__ u64c pk(float x, float y) {
    u64c r; asm("mov.b64 %0,{%1,%2};" : "=l"(r) : "f"(x), "f"(y)); return r;
}
__device__ __forceinline__ void upk(u64c a, float& x, float& y) {
    asm("mov.b64 {%0,%1},%2;" : "=f"(x), "=f"(y) : "l"(a));
}
__device__ __forceinline__ u64c fma2(u64c a, u64c b, u64c c) {
    u64c r; asm("fma.rn.f32x2 %0,%1,%2,%3;" : "=l"(r) : "l"(a), "l"(b), "l"(c)); return r;
}
__device__ __forceinline__ u64c mul2(u64c a, u64c b) {
    u64c r; asm("mul.rn.f32x2 %0,%1,%2;" : "=l"(r) : "l"(a), "l"(b)); return r;
}
// rotate packed complex a by phasor (cs,sn): (x cs - y sn, y cs + x sn)
__device__ __forceinline__ u64c crot(u64c a, u64c CS, u64c SN) {
    float x, y; upk(a, x, y);
    return fma2(pk(-y, x), SN, mul2(a, CS));
}

// Per-block Givens decomposition of all 23 gates into smem (threads 0..22).
// M = U^T = [[c e^{ia}, -s e^{i(a+d)}],[s e^{ib}, c e^{i(b+d)}]]
__device__ __forceinline__ void decompose(
    int tid, const float* __restrict__ ur, const float* __restrict__ ui,
    float* s_gc, float* s_gs, float* s_pre, float* s_post)
{
    if (tid < 23) {
        int k = tid;
        float m00r = ur[k*4+0], m00i = ui[k*4+0];
        float m01r = ur[k*4+2], m01i = ui[k*4+2];
        float m10r = ur[k*4+1], m10i = ui[k*4+1];
        float m11r = ur[k*4+3], m11i = ui[k*4+3];
        float c = sqrtf(m00r*m00r + m00i*m00i);
        float s = sqrtf(m10r*m10r + m10i*m10i);
        const float eps = 1e-20f;
        float a = (c > eps) ? atan2f(m00i, m00r) : 0.0f;
        float b = (s > eps) ? atan2f(m10i, m10r) : 0.0f;
        float d = (s > eps) ? (atan2f(-m01i, -m01r) - a)
                            : (atan2f(m11i, m11r) - b);
        int j = 22 - k;            // gate k acts on state bit 22-k
        s_gc[j] = c; s_gs[j] = s;
        s_pre[j] = d; s_post[j] = b - a;
    }
}

// Real Givens across a register bit rb: o0 = c*A0 - s*A1 ; o1 = s*A0 + c*A1
__device__ __forceinline__ void reg_gate_r(u64c (&a)[16], int rb, float c, float s)
{
    u64c cc = pk(c, c), ss = pk(s, s), ns = pk(-s, -s);
#pragma unroll
    for (int r0 = 0; r0 < 16; ++r0) {
        if (r0 & (1 << rb)) continue;
        int r1 = r0 | (1 << rb);
        u64c A0 = a[r0], A1 = a[r1];
        a[r0] = fma2(A1, ns, mul2(A0, cc));
        a[r1] = fma2(A1, cc, mul2(A0, ss));
    }
}

// Real Givens across a lane bit: new = c*me + t*other, t = myb ? s : -s
__device__ __forceinline__ void lane_gate_r(u64c (&a)[16], int mask, int myb,
                                            float c, float s)
{
    float t = myb ? s : -s;
    u64c cc = pk(c, c), tt = pk(t, t);
#pragma unroll
    for (int r = 0; r < 16; ++r) {
        float mx, my; upk(a[r], mx, my);
        float ox = __shfl_xor_sync(0xffffffffu, mx, mask);
        float oy = __shfl_xor_sync(0xffffffffu, my, mask);
        a[r] = fma2(pk(ox, oy), tt, mul2(a[r], cc));
    }
}

// ---------------------------------------------------------------------------
// Pass 1 (identical to R8 best): contiguous tiles of 8192 amps.
// m1 t1=(r<<9)|(w<<5)|lane: lane = state 0..4, warp = 5..8, reg = 9..12;
// restage swaps r<->w. Pre-phase over ALL 23 bits applied at load.
// ---------------------------------------------------------------------------
__global__ void __launch_bounds__(512, 2)
pass1_kernel(const float* __restrict__ c0r, const float* __restrict__ c0i,
             const float* __restrict__ ur,  const float* __restrict__ ui)
{
    __shared__ float s_gc[23], s_gs[23], s_pre[23], s_post[23];
    extern __shared__ u64c sm[];   // 8192 u64 = 64 KB restage buffer

    const int tid  = threadIdx.x;
    decompose(tid, ur, ui, s_gc, s_gs, s_pre, s_post);
    __syncthreads();

    const int lane = tid & 31;
    const int w    = tid >> 5;
    const unsigned bid  = blockIdx.x;
    const unsigned base = bid * 8192u;

    float th = 0.0f;
#pragma unroll
    for (int m = 0; m < 10; ++m)
        th += (float)((bid >> m) & 1u) * s_pre[13 + m];
#pragma unroll
    for (int j = 0; j < 5; ++j)
        th += (float)((lane >> j) & 1) * s_pre[j];
#pragma unroll
    for (int m = 0; m < 4; ++m)
        th += (float)((w >> m) & 1) * s_pre[5 + m];
    const float p9  = s_pre[9],  p10 = s_pre[10];
    const float p11 = s_pre[11], p12 = s_pre[12];

    u64c a[16];
#pragma unroll
    for (int r = 0; r < 16; ++r) {
        unsigned t1 = (unsigned)(r << 9) | (w << 5) | lane;
        float xr = __ldg(&c0r[base + t1]);
        float xi = __ldg(&c0i[base + t1]);
        float thr = th;
        if (r & 1) thr += p9;
        if (r & 2) thr += p10;
        if (r & 4) thr += p11;
        if (r & 8) thr += p12;
        float sn, cs; __sincosf(thr, &sn, &cs);
        a[r] = fma2(pk(xi, xr), pk(-sn, sn), mul2(pk(xr, xi), pk(cs, cs)));
    }

#pragma unroll
    for (int j = 0; j < 5; ++j)
        lane_gate_r(a, 1 << j, (lane >> j) & 1, s_gc[j], s_gs[j]);

#pragma unroll
    for (int rb = 0; rb < 4; ++rb)
        reg_gate_r(a, rb, s_gc[9 + rb], s_gs[9 + rb]);

#pragma unroll
    for (int r = 0; r < 16; ++r)
        sm[(unsigned)(r << 9) | (w << 5) | lane] = a[r];
    __syncthreads();
#pragma unroll
    for (int r = 0; r < 16; ++r)
        a[r] = sm[(unsigned)(w << 9) | (r << 5) | lane];

#pragma unroll
    for (int rb = 0; rb < 4; ++rb)
        reg_gate_r(a, rb, s_gc[5 + rb], s_gs[5 + rb]);

#pragma unroll
    for (int r = 0; r < 16; ++r)
        g_scratch[base + ((unsigned)(w << 9) | (r << 5) | lane)] = a[r];
}

// ---------------------------------------------------------------------------
// Pass 2: p = b&1 (L2 twin-sharing of c1), l0 = (b>>1)*8.
// tile bit j>=3 = state bit 10+j.
// m1 t1=(r<<9)|(w<<5)|lane: lane gates states 13,14 (tile3,4);
//   reg gates states 19..22 (tile9..12).
// Restage (swizzle j = i ^ ((i>>8)&1)) to m2:
//   lane' = {tile1,tile2,tile8,tile3,tile4}, r' = {tile0,tile5,tile6,tile7},
//   w = tile9..12. m2 gates: states 15,16,17 on r' bits 1..3 (reg);
//   state 18 on lane bit 2 (shfl).
// Dot: r' bit 0 = state bit 0 -> each thread owns address pairs -> float2
//   c1 loads, lanes tile the 8-float runs (full 32B sectors).
// Post: bits {0,15,16,17} via 16-entry table; rest thread-const end rotation.
// Last block: deterministic fixed-order reduction -> out[0].
// ---------------------------------------------------------------------------
__global__ void __launch_bounds__(512, 2)
pass2_kernel(const float* __restrict__ c1r, const float* __restrict__ c1i,
             const float* __restrict__ ur,  const float* __restrict__ ui,
             float* __restrict__ out)
{
    __shared__ float s_gc[23], s_gs[23], s_pre[23], s_post[23];
    __shared__ float s_ct[16], s_st[16];
    __shared__ float red[72];
    __shared__ int   s_isLast;
    extern __shared__ u64c sm[];

    const int tid  = threadIdx.x;
    decompose(tid, ur, ui, s_gc, s_gs, s_pre, s_post);
    __syncthreads();

    // 16-entry phasor table: ridx = (b0, b15, b16, b17)
    if (tid < 16) {
        float ang = (float)(tid & 1) * s_post[0];
#pragma unroll
        for (int m = 0; m < 3; ++m)
            ang += (float)((tid >> (1 + m)) & 1) * s_post[15 + m];
        float sn, cs; __sincosf(ang, &sn, &cs);
        s_ct[tid] = cs; s_st[tid] = sn;
    }

    const int lane = tid & 31;
    const int w    = tid >> 5;
    const int l0b  = lane & 1,        l1b = (lane >> 1) & 1;
    const int l2b  = (lane >> 2) & 1, l3b = (lane >> 3) & 1, l4b = (lane >> 4) & 1;
    const unsigned b  = blockIdx.x;
    const unsigned p  = b & 1u;
    const unsigned l0 = (b >> 1) * 8u;
    const unsigned stateBase = p << 23;

    u64c a[16];
#pragma unroll
    for (int r = 0; r < 16; ++r) {
        unsigned t1 = (unsigned)(r << 9) | (w << 5) | lane;
        unsigned s  = ((t1 >> 3) << 13) + l0 + (t1 & 7u);
        a[r] = __ldcg(&g_scratch[stateBase + s]);
    }

    // m1: lane gates states 13,14 (tile bits 3,4); reg gates states 19..22
    lane_gate_r(a, 1 << 3, l3b, s_gc[13], s_gs[13]);
    lane_gate_r(a, 1 << 4, l4b, s_gc[14], s_gs[14]);
#pragma unroll
    for (int rb = 0; rb < 4; ++rb)
        reg_gate_r(a, rb, s_gc[19 + rb], s_gs[19 + rb]);

    // restage m1 -> m2 with swizzle j = i ^ ((i>>8)&1)
#pragma unroll
    for (int r = 0; r < 16; ++r) {
        unsigned i = (unsigned)(r << 9) | (w << 5) | lane;
        sm[i ^ ((i >> 8) & 1u)] = a[r];
    }
    __syncthreads();
#pragma unroll
    for (int r = 0; r < 16; ++r) {
        unsigned i = (unsigned)(w << 9) | ((unsigned)l2b << 8)
                   | ((unsigned)(r >> 1) << 5)
                   | ((unsigned)l4b << 4) | ((unsigned)l3b << 3)
                   | ((unsigned)l1b << 2) | ((unsigned)l0b << 1)
                   | (unsigned)(r & 1);
        a[r] = sm[i ^ ((i >> 8) & 1u)];
    }

    // m2 gates: states 15,16,17 on reg bits 1..3; state 18 on lane bit 2
#pragma unroll
    for (int rb = 1; rb < 4; ++rb)
        reg_gate_r(a, rb, s_gc[14 + rb], s_gs[14 + rb]);
    lane_gate_r(a, 1 << 2, l2b, s_gc[18], s_gs[18]);

    // fused dot: per thread 8 address-pairs; float2 c1 loads
    const unsigned loOff = (unsigned)(l0b << 1) | (unsigned)(l1b << 2);
    const unsigned hiFix = (unsigned)(w << 6) | ((unsigned)l2b << 5)
                         | ((unsigned)l4b << 1) | (unsigned)l3b;
    float acc0 = 0.f, acc1 = 0.f, acc2 = 0.f, acc3 = 0.f;
#pragma unroll
    for (int rr = 0; rr < 8; ++rr) {
        unsigned hi = hiFix | ((unsigned)rr << 2);
        unsigned s  = (hi << 13) + l0 + loOff;
        const float2 X = *(const float2*)(c1r + s);
        const float2 I = *(const float2*)(c1i + s);
        const float2 Y = *(const float2*)(c1r + DIMQ + s);
        const float2 J = *(const float2*)(c1i + DIMQ + s);
#pragma unroll
        for (int k = 0; k < 2; ++k) {
            int ridx = rr*2 + k;
            float ct = s_ct[ridx], st = s_st[ridx];
            u64c d = crot(a[ridx], pk(ct, ct), pk(st, st));
            float dr, di; upk(d, dr, di);
            float xr = k ? X.y : X.x, xi = k ? I.y : I.x;
            acc0 += dr*xr + di*xi;
            acc1 += dr*xi - di*xr;
            float yr = k ? Y.y : Y.x, yi = k ? J.y : J.x;
            acc2 += dr*yr + di*yi;
            acc3 += dr*yi - di*yr;
        }
    }

    // end rotation: all thread-constant post bits
    {
        float thc = (float)l0b * s_post[1] + (float)l1b * s_post[2];
#pragma unroll
        for (int m = 0; m < 10; ++m)
            thc += (float)((b >> (1 + m)) & 1u) * s_post[3 + m];
        thc += (float)l3b * s_post[13];
        thc += (float)l4b * s_post[14];
        thc += (float)l2b * s_post[18];
#pragma unroll
        for (int m = 0; m < 4; ++m)
            thc += (float)((w >> m) & 1) * s_post[19 + m];
        float snc, csc; __sincosf(thc, &snc, &csc);
        float n0 = acc0*csc + acc1*snc, n1 = acc1*csc - acc0*snc;
        float n2 = acc2*csc + acc3*snc, n3 = acc3*csc - acc2*snc;
        acc0 = n0; acc1 = n1; acc2 = n2; acc3 = n3;
    }

#pragma unroll
    for (int o = 16; o > 0; o >>= 1) {
        acc0 += __shfl_xor_sync(0xffffffffu, acc0, o);
        acc1 += __shfl_xor_sync(0xffffffffu, acc1, o);
        acc2 += __shfl_xor_sync(0xffffffffu, acc2, o);
        acc3 += __shfl_xor_sync(0xffffffffu, acc3, o);
    }
    if (lane == 0) {
        red[w*4+0] = acc0; red[w*4+1] = acc1;
        red[w*4+2] = acc2; red[w*4+3] = acc3;
    }
    __syncthreads();
    if (tid < 4) {
        float s = 0.f;
#pragma unroll
        for (int k = 0; k < 16; ++k) s += red[k*4 + tid];
        red[64 + tid] = s;
    }
    __syncthreads();
    if (tid == 0) {
        g_partials[b*4+0] = red[64];
        g_partials[b*4+1] = red[65];
        g_partials[b*4+2] = red[66];
        g_partials[b*4+3] = red[67];
        __threadfence();
        unsigned ticket = atomicAdd(&g_count, 1u);
        s_isLast = (ticket == gridDim.x - 1u) ? 1 : 0;
    }
    __syncthreads();

    if (s_isLast) {
        float acc[8];
#pragma unroll
        for (int j = 0; j < 8; ++j) acc[j] = 0.f;
#pragma unroll
        for (int i = 0; i < 4; ++i) {
            unsigned bb = (unsigned)tid * 4u + i;
            unsigned pq = bb & 1u;
#pragma unroll
            for (int j = 0; j < 4; ++j)
                acc[pq*4 + j] += __ldcg(&g_partials[bb*4 + j]);
        }
#pragma unroll
        for (int o = 16; o > 0; o >>= 1)
#pragma unroll
            for (int j = 0; j < 8; ++j)
                acc[j] += __shfl_xor_sync(0xffffffffu, acc[j], o);
        float* r2 = (float*)sm;
        if (lane == 0)
#pragma unroll
            for (int j = 0; j < 8; ++j) r2[w*8 + j] = acc[j];
        __syncthreads();
        if (tid < 8) {
            float s = 0.f;
#pragma unroll
            for (int k = 0; k < 16; ++k) s += r2[k*8 + tid];
            r2[128 + tid] = s;
        }
        __syncthreads();
        if (tid == 0) {
            float s = 0.f;
#pragma unroll
            for (int j = 0; j < 8; ++j) s += r2[128 + j] * r2[128 + j];
            out[0] = 2.0f - s;
            g_count = 0;               // reset for next graph replay
        }
    }
}

// ---------------------------------------------------------------------------
extern "C" void kernel_launch(void* const* d_in, const int* in_sizes, int n_in,
                              void* d_out, int out_size)
{
    (void)in_sizes; (void)n_in; (void)out_size;
    const float* c0r = (const float*)d_in[0];
    const float* c0i = (const float*)d_in[1];
    const float* c1r = (const float*)d_in[2];
    const float* c1i = (const float*)d_in[3];
    const float* ur  = (const float*)d_in[4];
    const float* ui  = (const float*)d_in[5];

    cudaFuncSetAttribute(pass1_kernel, cudaFuncAttributeMaxDynamicSharedMemorySize, 65536);
    cudaFuncSetAttribute(pass2_kernel, cudaFuncAttributeMaxDynamicSharedMemorySize, 65536);

    pass1_kernel<<<2048, 512, 65536>>>(c0r, c0i, ur, ui);
    pass2_kernel<<<2048, 512, 65536>>>(c1r, c1i, ur, ui, (float*)d_out);
}

// round 11
// speedup vs baseline: 1.1957x; 1.0749x over previous
#include <cuda_runtime.h>
#include <math.h>

// ---------------------------------------------------------------------------
// QECCEqualModel via Givens decomposition (M_k = D1*G*D2):
//   D2 (all bits)  -> per-amp pre-phase at pass1 load
//   G              -> real Givens rotations
//   D1 bits 15..18 -> 16-entry phasor table applied per-register in pass2 dot
//   D1 all other   -> single thread-constant end rotation in pass2
// pass1: G on state bits 0..12, contiguous tiles -> scratch
// pass2: G on state bits 13..22 (gathered), fused dot with code1 with
//        one-iteration software prefetch, last-block reduction -> loss
// pass2 grid interleaves p in bit0 so p=0/p=1 twins share c1 via L2.
// ---------------------------------------------------------------------------

#define DIMQ (1u << 23)
typedef unsigned long long u64c;

__device__ u64c     g_scratch[2u * DIMQ];
__device__ float    g_partials[2048 * 4];
__device__ unsigned g_count;               // zero-init; reset by last block

__device__ __forceinline__ u64c pk(float x, float y) {
    u64c r; asm("mov.b64 %0,{%1,%2};" : "=l"(r) : "f"(x), "f"(y)); return r;
}
__device__ __forceinline__ void upk(u64c a, float& x, float& y) {
    asm("mov.b64 {%0,%1},%2;" : "=f"(x), "=f"(y) : "l"(a));
}
__device__ __forceinline__ u64c fma2(u64c a, u64c b, u64c c) {
    u64c r; asm("fma.rn.f32x2 %0,%1,%2,%3;" : "=l"(r) : "l"(a), "l"(b), "l"(c)); return r;
}
__device__ __forceinline__ u64c mul2(u64c a, u64c b) {
    u64c r; asm("mul.rn.f32x2 %0,%1,%2;" : "=l"(r) : "l"(a), "l"(b)); return r;
}
// rotate packed complex a by phasor (cs,sn): (x cs - y sn, y cs + x sn)
__device__ __forceinline__ u64c crot(u64c a, u64c CS, u64c SN) {
    float x, y; upk(a, x, y);
    return fma2(pk(-y, x), SN, mul2(a, CS));
}

// Per-block Givens decomposition of all 23 gates into smem (threads 0..22).
// M = U^T = [[c e^{ia}, -s e^{i(a+d)}],[s e^{ib}, c e^{i(b+d)}]]
__device__ __forceinline__ void decompose(
    int tid, const float* __restrict__ ur, const float* __restrict__ ui,
    float* s_gc, float* s_gs, float* s_pre, float* s_post)
{
    if (tid < 23) {
        int k = tid;
        float m00r = ur[k*4+0], m00i = ui[k*4+0];
        float m01r = ur[k*4+2], m01i = ui[k*4+2];
        float m10r = ur[k*4+1], m10i = ui[k*4+1];
        float m11r = ur[k*4+3], m11i = ui[k*4+3];
        float c = sqrtf(m00r*m00r + m00i*m00i);
        float s = sqrtf(m10r*m10r + m10i*m10i);
        const float eps = 1e-20f;
        float a = (c > eps) ? atan2f(m00i, m00r) : 0.0f;
        float b = (s > eps) ? atan2f(m10i, m10r) : 0.0f;
        float d = (s > eps) ? (atan2f(-m01i, -m01r) - a)
                            : (atan2f(m11i, m11r) - b);
        int j = 22 - k;            // gate k acts on state bit 22-k
        s_gc[j] = c; s_gs[j] = s;
        s_pre[j] = d; s_post[j] = b - a;
    }
}

// Real Givens across a register bit rb: o0 = c*A0 - s*A1 ; o1 = s*A0 + c*A1
__device__ __forceinline__ void reg_gate_r(u64c (&a)[16], int rb, float c, float s)
{
    u64c cc = pk(c, c), ss = pk(s, s), ns = pk(-s, -s);
#pragma unroll
    for (int r0 = 0; r0 < 16; ++r0) {
        if (r0 & (1 << rb)) continue;
        int r1 = r0 | (1 << rb);
        u64c A0 = a[r0], A1 = a[r1];
        a[r0] = fma2(A1, ns, mul2(A0, cc));
        a[r1] = fma2(A1, cc, mul2(A0, ss));
    }
}

// Real Givens across a lane bit: new = c*me + t*other, t = myb ? s : -s
__device__ __forceinline__ void lane_gate_r(u64c (&a)[16], int mask, int myb,
                                            float c, float s)
{
    float t = myb ? s : -s;
    u64c cc = pk(c, c), tt = pk(t, t);
#pragma unroll
    for (int r = 0; r < 16; ++r) {
        float mx, my; upk(a[r], mx, my);
        float ox = __shfl_xor_sync(0xffffffffu, mx, mask);
        float oy = __shfl_xor_sync(0xffffffffu, my, mask);
        a[r] = fma2(pk(ox, oy), tt, mul2(a[r], cc));
    }
}

// ---------------------------------------------------------------------------
// Pass 1: contiguous tiles of 8192 amps. m1 t1=(r<<9)|(w<<5)|lane:
// lane = state 0..4, warp = 5..8, reg = 9..12; restage swaps r<->w.
// Pre-phase over ALL 23 bits applied at load.
// ---------------------------------------------------------------------------
__global__ void __launch_bounds__(512, 2)
pass1_kernel(const float* __restrict__ c0r, const float* __restrict__ c0i,
             const float* __restrict__ ur,  const float* __restrict__ ui)
{
    __shared__ float s_gc[23], s_gs[23], s_pre[23], s_post[23];
    extern __shared__ u64c sm[];   // 8192 u64 = 64 KB restage buffer

    const int tid  = threadIdx.x;
    decompose(tid, ur, ui, s_gc, s_gs, s_pre, s_post);
    __syncthreads();

    const int lane = tid & 31;
    const int w    = tid >> 5;
    const unsigned bid  = blockIdx.x;
    const unsigned base = bid * 8192u;

    // fixed part of pre-phase angle (bid bits 0..9 = state bits 13..22)
    float th = 0.0f;
#pragma unroll
    for (int m = 0; m < 10; ++m)
        th += (float)((bid >> m) & 1u) * s_pre[13 + m];
#pragma unroll
    for (int j = 0; j < 5; ++j)
        th += (float)((lane >> j) & 1) * s_pre[j];
#pragma unroll
    for (int m = 0; m < 4; ++m)
        th += (float)((w >> m) & 1) * s_pre[5 + m];
    const float p9  = s_pre[9],  p10 = s_pre[10];
    const float p11 = s_pre[11], p12 = s_pre[12];

    u64c a[16];
#pragma unroll
    for (int r = 0; r < 16; ++r) {
        unsigned t1 = (unsigned)(r << 9) | (w << 5) | lane;
        float xr = __ldg(&c0r[base + t1]);
        float xi = __ldg(&c0i[base + t1]);
        float thr = th;
        if (r & 1) thr += p9;
        if (r & 2) thr += p10;
        if (r & 4) thr += p11;
        if (r & 8) thr += p12;
        float sn, cs; __sincosf(thr, &sn, &cs);
        a[r] = fma2(pk(xi, xr), pk(-sn, sn), mul2(pk(xr, xi), pk(cs, cs)));
    }

#pragma unroll
    for (int j = 0; j < 5; ++j)
        lane_gate_r(a, 1 << j, (lane >> j) & 1, s_gc[j], s_gs[j]);

#pragma unroll
    for (int rb = 0; rb < 4; ++rb)
        reg_gate_r(a, rb, s_gc[9 + rb], s_gs[9 + rb]);

#pragma unroll
    for (int r = 0; r < 16; ++r)
        sm[(unsigned)(r << 9) | (w << 5) | lane] = a[r];
    __syncthreads();
#pragma unroll
    for (int r = 0; r < 16; ++r)
        a[r] = sm[(unsigned)(w << 9) | (r << 5) | lane];

#pragma unroll
    for (int rb = 0; rb < 4; ++rb)
        reg_gate_r(a, rb, s_gc[5 + rb], s_gs[5 + rb]);

#pragma unroll
    for (int r = 0; r < 16; ++r)
        g_scratch[base + ((unsigned)(w << 9) | (r << 5) | lane)] = a[r];
}

// ---------------------------------------------------------------------------
// Pass 2: p = b&1 (L2 twin-sharing of c1), l0 = (b>>1)*8.
// Gathered tiles (2^10 high combos x 8 contiguous low), fused dot.
// tile bit j>=3 = state bit 10+j:
//   lane gates: tile bits 3,4 -> state 13,14
//   reg m1: tile bits 9..12 -> state 19..22
//   restage; reg m2: tile bits 5..8 -> state 15..18
// Post-phase: states 15..18 depend only on r -> 16-entry smem phasor table;
// everything else is thread-constant -> one end rotation.
// Dot is software-pipelined: iteration r+1's c1 loads issue before
// iteration r's FMAs consume (MLP 4 -> 8).
// Last block: deterministic fixed-order reduction -> out[0].
// ---------------------------------------------------------------------------
__global__ void __launch_bounds__(512, 2)
pass2_kernel(const float* __restrict__ c1r, const float* __restrict__ c1i,
             const float* __restrict__ ur,  const float* __restrict__ ui,
             float* __restrict__ out)
{
    __shared__ float s_gc[23], s_gs[23], s_pre[23], s_post[23];
    __shared__ float s_ct[16], s_st[16];
    __shared__ float red[72];
    __shared__ int   s_isLast;
    extern __shared__ u64c sm[];

    const int tid  = threadIdx.x;
    decompose(tid, ur, ui, s_gc, s_gs, s_pre, s_post);
    __syncthreads();

    // 16-entry phasor table for r-dependent post bits (states 15..18)
    if (tid < 16) {
        float ang = 0.0f;
#pragma unroll
        for (int m = 0; m < 4; ++m)
            ang += (float)((tid >> m) & 1) * s_post[15 + m];
        float sn, cs; __sincosf(ang, &sn, &cs);
        s_ct[tid] = cs; s_st[tid] = sn;
    }

    const int lane = tid & 31;
    const int w    = tid >> 5;
    const unsigned b  = blockIdx.x;
    const unsigned p  = b & 1u;
    const unsigned l0 = (b >> 1) * 8u;
    const unsigned stateBase = p << 23;

    u64c a[16];
#pragma unroll
    for (int r = 0; r < 16; ++r) {
        unsigned t1 = (unsigned)(r << 9) | (w << 5) | lane;
        unsigned s  = ((t1 >> 3) << 13) + l0 + (t1 & 7u);
        a[r] = g_scratch[stateBase + s];
    }

    // m1: lane gates state 13,14 (tile bits 3,4); reg gates states 19..22
    lane_gate_r(a, 1 << 3, (lane >> 3) & 1, s_gc[13], s_gs[13]);
    lane_gate_r(a, 1 << 4, (lane >> 4) & 1, s_gc[14], s_gs[14]);
#pragma unroll
    for (int rb = 0; rb < 4; ++rb)
        reg_gate_r(a, rb, s_gc[19 + rb], s_gs[19 + rb]);

    // restage m1 -> m2 (swap reg bits <-> warp bits); also orders s_ct/s_st
#pragma unroll
    for (int r = 0; r < 16; ++r)
        sm[(unsigned)(r << 9) | (w << 5) | lane] = a[r];
    __syncthreads();
#pragma unroll
    for (int r = 0; r < 16; ++r)
        a[r] = sm[(unsigned)(w << 9) | (r << 5) | lane];

    // m2 reg gates: states 15..18 (tile bits 5..8 = r bits)
#pragma unroll
    for (int rb = 0; rb < 4; ++rb)
        reg_gate_r(a, rb, s_gc[15 + rb], s_gs[15 + rb]);

    // fused dot with per-r table phasor; software-pipelined c1 loads.
    // s(r) = base + r * 2^15  (t2 = (w<<9)|(r<<5)|lane)
    const unsigned sB = (((unsigned)(w << 6) | (unsigned)(lane >> 3)) << 13)
                      + l0 + (unsigned)(lane & 7);
    float acc0 = 0.f, acc1 = 0.f, acc2 = 0.f, acc3 = 0.f;
    unsigned sp = sB;
    float nxr = __ldg(&c1r[sp]),        nxi = __ldg(&c1i[sp]);
    float nyr = __ldg(&c1r[DIMQ + sp]), nyi = __ldg(&c1i[DIMQ + sp]);
#pragma unroll
    for (int r = 0; r < 16; ++r) {
        float xr = nxr, xi = nxi, yr = nyr, yi = nyi;
        if (r < 15) {
            sp += (1u << 15);
            nxr = __ldg(&c1r[sp]);        nxi = __ldg(&c1i[sp]);
            nyr = __ldg(&c1r[DIMQ + sp]); nyi = __ldg(&c1i[DIMQ + sp]);
        }
        float ct = s_ct[r], st = s_st[r];
        u64c d = crot(a[r], pk(ct, ct), pk(st, st));
        float dr, di; upk(d, dr, di);
        acc0 += dr*xr + di*xi;
        acc1 += dr*xi - di*xr;
        acc2 += dr*yr + di*yi;
        acc3 += dr*yi - di*yr;
    }

    // end rotation: all thread-constant post bits
    {
        float thc = (float)(lane & 1)        * s_post[0]
                  + (float)((lane >> 1) & 1) * s_post[1]
                  + (float)((lane >> 2) & 1) * s_post[2];
#pragma unroll
        for (int m = 0; m < 10; ++m)
            thc += (float)((b >> (1 + m)) & 1u) * s_post[3 + m];
        thc += (float)((lane >> 3) & 1) * s_post[13];
        thc += (float)((lane >> 4) & 1) * s_post[14];
#pragma unroll
        for (int m = 0; m < 4; ++m)
            thc += (float)((w >> m) & 1) * s_post[19 + m];
        float snc, csc; __sincosf(thc, &snc, &csc);
        float n0 = acc0*csc + acc1*snc, n1 = acc1*csc - acc0*snc;
        float n2 = acc2*csc + acc3*snc, n3 = acc3*csc - acc2*snc;
        acc0 = n0; acc1 = n1; acc2 = n2; acc3 = n3;
    }

#pragma unroll
    for (int o = 16; o > 0; o >>= 1) {
        acc0 += __shfl_xor_sync(0xffffffffu, acc0, o);
        acc1 += __shfl_xor_sync(0xffffffffu, acc1, o);
        acc2 += __shfl_xor_sync(0xffffffffu, acc2, o);
        acc3 += __shfl_xor_sync(0xffffffffu, acc3, o);
    }
    if (lane == 0) {
        red[w*4+0] = acc0; red[w*4+1] = acc1;
        red[w*4+2] = acc2; red[w*4+3] = acc3;
    }
    __syncthreads();
    if (tid < 4) {
        float s = 0.f;
#pragma unroll
        for (int k = 0; k < 16; ++k) s += red[k*4 + tid];
        red[64 + tid] = s;
    }
    __syncthreads();
    if (tid == 0) {
        g_partials[b*4+0] = red[64];
        g_partials[b*4+1] = red[65];
        g_partials[b*4+2] = red[66];
        g_partials[b*4+3] = red[67];
        __threadfence();
        unsigned ticket = atomicAdd(&g_count, 1u);
        s_isLast = (ticket == gridDim.x - 1u) ? 1 : 0;
    }
    __syncthreads();

    if (s_isLast) {
        float acc[8];
#pragma unroll
        for (int j = 0; j < 8; ++j) acc[j] = 0.f;
#pragma unroll
        for (int i = 0; i < 4; ++i) {
            unsigned bb = (unsigned)tid * 4u + i;
            unsigned pq = bb & 1u;
#pragma unroll
            for (int j = 0; j < 4; ++j)
                acc[pq*4 + j] += __ldcg(&g_partials[bb*4 + j]);
        }
#pragma unroll
        for (int o = 16; o > 0; o >>= 1)
#pragma unroll
            for (int j = 0; j < 8; ++j)
                acc[j] += __shfl_xor_sync(0xffffffffu, acc[j], o);
        float* r2 = (float*)sm;
        if (lane == 0)
#pragma unroll
            for (int j = 0; j < 8; ++j) r2[w*8 + j] = acc[j];
        __syncthreads();
        if (tid < 8) {
            float s = 0.f;
#pragma unroll
            for (int k = 0; k < 16; ++k) s += r2[k*8 + tid];
            r2[128 + tid] = s;
        }
        __syncthreads();
        if (tid == 0) {
            float s = 0.f;
#pragma unroll
            for (int j = 0; j < 8; ++j) s += r2[128 + j] * r2[128 + j];
            out[0] = 2.0f - s;
            g_count = 0;               // reset for next graph replay
        }
    }
}

// ---------------------------------------------------------------------------
extern "C" void kernel_launch(void* const* d_in, const int* in_sizes, int n_in,
                              void* d_out, int out_size)
{
    (void)in_sizes; (void)n_in; (void)out_size;
    const float* c0r = (const float*)d_in[0];
    const float* c0i = (const float*)d_in[1];
    const float* c1r = (const float*)d_in[2];
    const float* c1i = (const float*)d_in[3];
    const float* ur  = (const float*)d_in[4];
    const float* ui  = (const float*)d_in[5];

    cudaFuncSetAttribute(pass1_kernel, cudaFuncAttributeMaxDynamicSharedMemorySize, 65536);
    cudaFuncSetAttribute(pass2_kernel, cudaFuncAttributeMaxDynamicSharedMemorySize, 65536);

    pass1_kernel<<<2048, 512, 65536>>>(c0r, c0i, ur, ui);
    pass2_kernel<<<2048, 512, 65536>>>(c1r, c1i, ur, ui, (float*)d_out);
}

// round 12
// speedup vs baseline: 1.2125x; 1.0141x over previous
#include <cuda_runtime.h>
#include <math.h>

// ---------------------------------------------------------------------------
// QECCEqualModel via Givens decomposition (M_k = D1*G*D2):
//   D2 bits 9..12  -> 16-entry phasor table at pass1 load
//   D2 all other   -> one thread-constant rotation at pass1 load
//   G              -> real Givens rotations
//   D1 bits 15..18 -> 16-entry phasor table applied per-register in pass2 dot
//   D1 all other   -> single thread-constant end rotation in pass2
// pass1: G on state bits 0..12, contiguous tiles -> scratch
// pass2: G on state bits 13..22 (gathered), fused dot with code1,
//        last-block deterministic reduction -> loss  (2 launches total)
// pass2 grid interleaves p in bit0 so p=0/p=1 twins share c1 via L2.
// ---------------------------------------------------------------------------

#define DIMQ (1u << 23)
typedef unsigned long long u64c;

__device__ u64c     g_scratch[2u * DIMQ];
__device__ float    g_partials[2048 * 4];
__device__ unsigned g_count;               // zero-init; reset by last block

__device__ __forceinline__ u64c pk(float x, float y) {
    u64c r; asm("mov.b64 %0,{%1,%2};" : "=l"(r) : "f"(x), "f"(y)); return r;
}
__device__ __forceinline__ void upk(u64c a, float& x, float& y) {
    asm("mov.b64 {%0,%1},%2;" : "=f"(x), "=f"(y) : "l"(a));
}
__device__ __forceinline__ u64c fma2(u64c a, u64c b, u64c c) {
    u64c r; asm("fma.rn.f32x2 %0,%1,%2,%3;" : "=l"(r) : "l"(a), "l"(b), "l"(c)); return r;
}
__device__ __forceinline__ u64c mul2(u64c a, u64c b) {
    u64c r; asm("mul.rn.f32x2 %0,%1,%2;" : "=l"(r) : "l"(a), "l"(b)); return r;
}
// rotate packed complex a by phasor (cs,sn): (x cs - y sn, y cs + x sn)
__device__ __forceinline__ u64c crot(u64c a, u64c CS, u64c SN) {
    float x, y; upk(a, x, y);
    return fma2(pk(-y, x), SN, mul2(a, CS));
}
// rotate by packed phasor (cs,sn) held in one u64
__device__ __forceinline__ u64c crotp(u64c a, u64c P) {
    float cs, sn; upk(P, cs, sn);
    float x, y; upk(a, x, y);
    return fma2(pk(-y, x), pk(sn, sn), mul2(a, pk(cs, cs)));
}

// Per-block Givens decomposition of all 23 gates into smem (threads 0..22).
// M = U^T = [[c e^{ia}, -s e^{i(a+d)}],[s e^{ib}, c e^{i(b+d)}]]
__device__ __forceinline__ void decompose(
    int tid, const float* __restrict__ ur, const float* __restrict__ ui,
    float* s_gc, float* s_gs, float* s_pre, float* s_post)
{
    if (tid < 23) {
        int k = tid;
        float m00r = ur[k*4+0], m00i = ui[k*4+0];
        float m01r = ur[k*4+2], m01i = ui[k*4+2];
        float m10r = ur[k*4+1], m10i = ui[k*4+1];
        float m11r = ur[k*4+3], m11i = ui[k*4+3];
        float c = sqrtf(m00r*m00r + m00i*m00i);
        float s = sqrtf(m10r*m10r + m10i*m10i);
        const float eps = 1e-20f;
        float a = (c > eps) ? atan2f(m00i, m00r) : 0.0f;
        float b = (s > eps) ? atan2f(m10i, m10r) : 0.0f;
        float d = (s > eps) ? (atan2f(-m01i, -m01r) - a)
                            : (atan2f(m11i, m11r) - b);
        int j = 22 - k;            // gate k acts on state bit 22-k
        s_gc[j] = c; s_gs[j] = s;
        s_pre[j] = d; s_post[j] = b - a;
    }
}

// Real Givens across a register bit rb: o0 = c*A0 - s*A1 ; o1 = s*A0 + c*A1
__device__ __forceinline__ void reg_gate_r(u64c (&a)[16], int rb, float c, float s)
{
    u64c cc = pk(c, c), ss = pk(s, s), ns = pk(-s, -s);
#pragma unroll
    for (int r0 = 0; r0 < 16; ++r0) {
        if (r0 & (1 << rb)) continue;
        int r1 = r0 | (1 << rb);
        u64c A0 = a[r0], A1 = a[r1];
        a[r0] = fma2(A1, ns, mul2(A0, cc));
        a[r1] = fma2(A1, cc, mul2(A0, ss));
    }
}

// Real Givens across a lane bit: new = c*me + t*other, t = myb ? s : -s
__device__ __forceinline__ void lane_gate_r(u64c (&a)[16], int mask, int myb,
                                            float c, float s)
{
    float t = myb ? s : -s;
    u64c cc = pk(c, c), tt = pk(t, t);
#pragma unroll
    for (int r = 0; r < 16; ++r) {
        float mx, my; upk(a[r], mx, my);
        float ox = __shfl_xor_sync(0xffffffffu, mx, mask);
        float oy = __shfl_xor_sync(0xffffffffu, my, mask);
        a[r] = fma2(pk(ox, oy), tt, mul2(a[r], cc));
    }
}

// ---------------------------------------------------------------------------
// Pass 1: contiguous tiles of 8192 amps. m1 t1=(r<<9)|(w<<5)|lane:
// lane = state 0..4, warp = 5..8, reg = 9..12; restage swaps r<->w.
// Pre-phase: bits 9..12 via packed phasor table, rest one thread sincos.
// ---------------------------------------------------------------------------
__global__ void __launch_bounds__(512, 2)
pass1_kernel(const float* __restrict__ c0r, const float* __restrict__ c0i,
             const float* __restrict__ ur,  const float* __restrict__ ui)
{
    __shared__ float s_gc[23], s_gs[23], s_pre[23], s_post[23];
    __shared__ u64c  s_pt[16];     // packed (cs,sn) phasors for pre bits 9..12
    extern __shared__ u64c sm[];   // 8192 u64 = 64 KB restage buffer

    const int tid  = threadIdx.x;
    decompose(tid, ur, ui, s_gc, s_gs, s_pre, s_post);
    __syncthreads();

    if (tid < 16) {
        float ang = 0.0f;
#pragma unroll
        for (int m = 0; m < 4; ++m)
            ang += (float)((tid >> m) & 1) * s_pre[9 + m];
        float sn, cs; __sincosf(ang, &sn, &cs);
        s_pt[tid] = pk(cs, sn);
    }
    __syncthreads();

    const int lane = tid & 31;
    const int w    = tid >> 5;
    const unsigned bid  = blockIdx.x;
    const unsigned base = bid * 8192u;

    // thread-constant pre-phase (bid bits 0..9 = state bits 13..22)
    float th = 0.0f;
#pragma unroll
    for (int m = 0; m < 10; ++m)
        th += (float)((bid >> m) & 1u) * s_pre[13 + m];
#pragma unroll
    for (int j = 0; j < 5; ++j)
        th += (float)((lane >> j) & 1) * s_pre[j];
#pragma unroll
    for (int m = 0; m < 4; ++m)
        th += (float)((w >> m) & 1) * s_pre[5 + m];
    float snT, csT; __sincosf(th, &snT, &csT);
    const u64c TC = pk(csT, csT), TS = pk(snT, snT);

    u64c a[16];
#pragma unroll
    for (int r = 0; r < 16; ++r) {
        unsigned t1 = (unsigned)(r << 9) | (w << 5) | lane;
        float xr = __ldg(&c0r[base + t1]);
        float xi = __ldg(&c0i[base + t1]);
        u64c x = crotp(pk(xr, xi), s_pt[r]);
        a[r] = crot(x, TC, TS);
    }

#pragma unroll
    for (int j = 0; j < 5; ++j)
        lane_gate_r(a, 1 << j, (lane >> j) & 1, s_gc[j], s_gs[j]);

#pragma unroll
    for (int rb = 0; rb < 4; ++rb)
        reg_gate_r(a, rb, s_gc[9 + rb], s_gs[9 + rb]);

#pragma unroll
    for (int r = 0; r < 16; ++r)
        sm[(unsigned)(r << 9) | (w << 5) | lane] = a[r];
    __syncthreads();
#pragma unroll
    for (int r = 0; r < 16; ++r)
        a[r] = sm[(unsigned)(w << 9) | (r << 5) | lane];

#pragma unroll
    for (int rb = 0; rb < 4; ++rb)
        reg_gate_r(a, rb, s_gc[5 + rb], s_gs[5 + rb]);

#pragma unroll
    for (int r = 0; r < 16; ++r)
        g_scratch[base + ((unsigned)(w << 9) | (r << 5) | lane)] = a[r];
}

// ---------------------------------------------------------------------------
// Pass 2: p = b&1 (L2 twin-sharing of c1), l0 = (b>>1)*8.
// Gathered tiles (2^10 high combos x 8 contiguous low), fused dot.
// tile bit j>=3 = state bit 10+j:
//   lane gates: tile bits 3,4 -> state 13,14
//   reg m1: tile bits 9..12 -> state 19..22
//   restage; reg m2: tile bits 5..8 -> state 15..18
// Post-phase: states 15..18 via packed 16-entry phasor table (per r);
// everything else is thread-constant -> one end rotation.
// Last block: deterministic fixed-order reduction -> out[0].
// ---------------------------------------------------------------------------
__global__ void __launch_bounds__(512, 2)
pass2_kernel(const float* __restrict__ c1r, const float* __restrict__ c1i,
             const float* __restrict__ ur,  const float* __restrict__ ui,
             float* __restrict__ out)
{
    __shared__ float s_gc[23], s_gs[23], s_pre[23], s_post[23];
    __shared__ u64c  s_qt[16];     // packed (cs,sn) phasors for post 15..18
    __shared__ float red[72];
    __shared__ int   s_isLast;
    extern __shared__ u64c sm[];

    const int tid  = threadIdx.x;
    decompose(tid, ur, ui, s_gc, s_gs, s_pre, s_post);
    __syncthreads();

    if (tid < 16) {
        float ang = 0.0f;
#pragma unroll
        for (int m = 0; m < 4; ++m)
            ang += (float)((tid >> m) & 1) * s_post[15 + m];
        float sn, cs; __sincosf(ang, &sn, &cs);
        s_qt[tid] = pk(cs, sn);
    }

    const int lane = tid & 31;
    const int w    = tid >> 5;
    const unsigned b  = blockIdx.x;
    const unsigned p  = b & 1u;
    const unsigned l0 = (b >> 1) * 8u;
    const unsigned stateBase = p << 23;

    u64c a[16];
#pragma unroll
    for (int r = 0; r < 16; ++r) {
        unsigned t1 = (unsigned)(r << 9) | (w << 5) | lane;
        unsigned s  = ((t1 >> 3) << 13) + l0 + (t1 & 7u);
        a[r] = g_scratch[stateBase + s];
    }

    // m1: lane gates state 13,14 (tile bits 3,4); reg gates states 19..22
    lane_gate_r(a, 1 << 3, (lane >> 3) & 1, s_gc[13], s_gs[13]);
    lane_gate_r(a, 1 << 4, (lane >> 4) & 1, s_gc[14], s_gs[14]);
#pragma unroll
    for (int rb = 0; rb < 4; ++rb)
        reg_gate_r(a, rb, s_gc[19 + rb], s_gs[19 + rb]);

    // restage m1 -> m2 (swap reg bits <-> warp bits); also orders s_qt
#pragma unroll
    for (int r = 0; r < 16; ++r)
        sm[(unsigned)(r << 9) | (w << 5) | lane] = a[r];
    __syncthreads();
#pragma unroll
    for (int r = 0; r < 16; ++r)
        a[r] = sm[(unsigned)(w << 9) | (r << 5) | lane];

    // m2 reg gates: states 15..18 (tile bits 5..8 = r bits)
#pragma unroll
    for (int rb = 0; rb < 4; ++rb)
        reg_gate_r(a, rb, s_gc[15 + rb], s_gs[15 + rb]);

    // fused dot with per-r packed table phasor; pipelined c1 loads.
    // s(r) = base + r * 2^15  (t2 = (w<<9)|(r<<5)|lane)
    const unsigned sB = (((unsigned)(w << 6) | (unsigned)(lane >> 3)) << 13)
                      + l0 + (unsigned)(lane & 7);
    float acc0 = 0.f, acc1 = 0.f, acc2 = 0.f, acc3 = 0.f;
    unsigned sp = sB;
    float nxr = __ldg(&c1r[sp]),        nxi = __ldg(&c1i[sp]);
    float nyr = __ldg(&c1r[DIMQ + sp]), nyi = __ldg(&c1i[DIMQ + sp]);
#pragma unroll
    for (int r = 0; r < 16; ++r) {
        float xr = nxr, xi = nxi, yr = nyr, yi = nyi;
        if (r < 15) {
            sp += (1u << 15);
            nxr = __ldg(&c1r[sp]);        nxi = __ldg(&c1i[sp]);
            nyr = __ldg(&c1r[DIMQ + sp]); nyi = __ldg(&c1i[DIMQ + sp]);
        }
        u64c d = crotp(a[r], s_qt[r]);
        float dr, di; upk(d, dr, di);
        acc0 += dr*xr + di*xi;
        acc1 += dr*xi - di*xr;
        acc2 += dr*yr + di*yi;
        acc3 += dr*yi - di*yr;
    }

    // end rotation: all thread-constant post bits
    {
        float thc = (float)(lane & 1)        * s_post[0]
                  + (float)((lane >> 1) & 1) * s_post[1]
                  + (float)((lane >> 2) & 1) * s_post[2];
#pragma unroll
        for (int m = 0; m < 10; ++m)
            thc += (float)((b >> (1 + m)) & 1u) * s_post[3 + m];
        thc += (float)((lane >> 3) & 1) * s_post[13];
        thc += (float)((lane >> 4) & 1) * s_post[14];
#pragma unroll
        for (int m = 0; m < 4; ++m)
            thc += (float)((w >> m) & 1) * s_post[19 + m];
        float snc, csc; __sincosf(thc, &snc, &csc);
        float n0 = acc0*csc + acc1*snc, n1 = acc1*csc - acc0*snc;
        float n2 = acc2*csc + acc3*snc, n3 = acc3*csc - acc2*snc;
        acc0 = n0; acc1 = n1; acc2 = n2; acc3 = n3;
    }

#pragma unroll
    for (int o = 16; o > 0; o >>= 1) {
        acc0 += __shfl_xor_sync(0xffffffffu, acc0, o);
        acc1 += __shfl_xor_sync(0xffffffffu, acc1, o);
        acc2 += __shfl_xor_sync(0xffffffffu, acc2, o);
        acc3 += __shfl_xor_sync(0xffffffffu, acc3, o);
    }
    if (lane == 0) {
        red[w*4+0] = acc0; red[w*4+1] = acc1;
        red[w*4+2] = acc2; red[w*4+3] = acc3;
    }
    __syncthreads();
    if (tid < 4) {
        float s = 0.f;
#pragma unroll
        for (int k = 0; k < 16; ++k) s += red[k*4 + tid];
        red[64 + tid] = s;
    }
    __syncthreads();
    if (tid == 0) {
        g_partials[b*4+0] = red[64];
        g_partials[b*4+1] = red[65];
        g_partials[b*4+2] = red[66];
        g_partials[b*4+3] = red[67];
        __threadfence();
        unsigned ticket = atomicAdd(&g_count, 1u);
        s_isLast = (ticket == gridDim.x - 1u) ? 1 : 0;
    }
    __syncthreads();

    if (s_isLast) {
        float acc[8];
#pragma unroll
        for (int j = 0; j < 8; ++j) acc[j] = 0.f;
#pragma unroll
        for (int i = 0; i < 4; ++i) {
            unsigned bb = (unsigned)tid * 4u + i;
            unsigned pq = bb & 1u;
#pragma unroll
            for (int j = 0; j < 4; ++j)
                acc[pq*4 + j] += __ldcg(&g_partials[bb*4 + j]);
        }
#pragma unroll
        for (int o = 16; o > 0; o >>= 1)
#pragma unroll
            for (int j = 0; j < 8; ++j)
                acc[j] += __shfl_xor_sync(0xffffffffu, acc[j], o);
        float* r2 = (float*)sm;
        if (lane == 0)
#pragma unroll
            for (int j = 0; j < 8; ++j) r2[w*8 + j] = acc[j];
        __syncthreads();
        if (tid < 8) {
            float s = 0.f;
#pragma unroll
            for (int k = 0; k < 16; ++k) s += r2[k*8 + tid];
            r2[128 + tid] = s;
        }
        __syncthreads();
        if (tid == 0) {
            float s = 0.f;
#pragma unroll
            for (int j = 0; j < 8; ++j) s += r2[128 + j] * r2[128 + j];
            out[0] = 2.0f - s;
            g_count = 0;               // reset for next graph replay
        }
    }
}

// ---------------------------------------------------------------------------
extern "C" void kernel_launch(void* const* d_in, const int* in_sizes, int n_in,
                              void* d_out, int out_size)
{
    (void)in_sizes; (void)n_in; (void)out_size;
    const float* c0r = (const float*)d_in[0];
    const float* c0i = (const float*)d_in[1];
    const float* c1r = (const float*)d_in[2];
    const float* c1i = (const float*)d_in[3];
    const float* ur  = (const float*)d_in[4];
    const float* ui  = (const float*)d_in[5];

    cudaFuncSetAttribute(pass1_kernel, cudaFuncAttributeMaxDynamicSharedMemorySize, 65536);
    cudaFuncSetAttribute(pass2_kernel, cudaFuncAttributeMaxDynamicSharedMemorySize, 65536);

    pass1_kernel<<<2048, 512, 65536>>>(c0r, c0i, ur, ui);
    pass2_kernel<<<2048, 512, 65536>>>(c1r, c1i, ur, ui, (float*)d_out);
}